// round 2
// baseline (speedup 1.0000x reference)
#include <cuda_runtime.h>
#include <math.h>
#include <stdint.h>

// Problem dims
#define Bb   256
#define Tt   256
#define INP  2
#define Ss   2
#define Hh   1024
#define Zz   1026      // S + H
#define KW   1028      // WU_w inner dim = IN + S + H

// Output buffer layout (flattened pytree of the reference return):
// outputs (B,T,Z) | zf (1,B,Z) | czf (1,B,Z) | coefficients (B,T,S) | mats (T,2,2)
#define OUT_OFF  0ll
#define ZF_OFF   ((long long)Bb * Tt * Zz)
#define CZF_OFF  (ZF_OFF + (long long)Bb * Zz)
#define COEF_OFF (CZF_OFF + (long long)Bb * Zz)
#define MATS_OFF (COEF_OFF + (long long)Bb * Tt * Ss)

// Persistent state (device globals — no allocation allowed)
__device__ float g_h[2][Bb * Hh];   // ping-pong hidden state
__device__ float g_c[Bb * Hh];      // cell state (in-place update)
__device__ float g_x[Bb * Ss];      // dynamical state

__device__ __forceinline__ float sigm(float x) {
    return 1.0f / (1.0f + expf(-x));
}

// ---------------------------------------------------------------------------
// init: load z0 / c_z0 into state buffers
// ---------------------------------------------------------------------------
__global__ void init_state(const float* __restrict__ z0,
                           const float* __restrict__ c_z0) {
    int i = blockIdx.x * blockDim.x + threadIdx.x;
    if (i < Bb * Hh) {
        int b = i / Hh, j = i - b * Hh;
        g_h[0][i] = z0[(size_t)b * Zz + 2 + j];
        g_c[i]    = c_z0[(size_t)b * Zz + 2 + j];
    }
    if (i < Bb * Ss) {
        int b = i / Ss, s = i - b * Ss;
        g_x[i] = z0[(size_t)b * Zz + s];
    }
}

// ---------------------------------------------------------------------------
// Kernel A: gates GEMM (h @ Wh^T) fused with x/input columns, bias,
// and the full LSTM pointwise update. Each CTA: 64 batch rows x 16 hidden
// units (i.e. 64x64 gate values, all 4 gates per hidden unit).
// Grid: (B/64, H/16) = (4, 64). Block: 128 threads.
// ---------------------------------------------------------------------------
#define BM   64
#define BHU  16
#define BK   32
#define HPAD 68
#define WPAD 68

__global__ __launch_bounds__(128) void gates_lstm(
    const float* __restrict__ WU_w,      // (4096, 1028) row-major
    const float* __restrict__ WU_b,      // (4096)
    const float* __restrict__ rnn_input, // (B, T, IN)
    float* __restrict__ out,             // d_out
    int t)
{
    __shared__ float sh_h[BK][HPAD];     // [k][m]
    __shared__ float sh_w[BK][WPAD];     // [k][n*4+g]

    const float* __restrict__ h_in  = g_h[t & 1];
    float*       __restrict__ h_out = g_h[(t & 1) ^ 1];

    int tid = threadIdx.x;
    int tx  = tid & 7;    // 2 hidden units each
    int ty  = tid >> 3;   // 4 batch rows each (0..15)
    int m0  = blockIdx.x * BM;
    int n0  = blockIdx.y * BHU;

    float acc[4][2][4];
    #pragma unroll
    for (int mi = 0; mi < 4; mi++)
        #pragma unroll
        for (int ni = 0; ni < 2; ni++)
            #pragma unroll
            for (int g = 0; g < 4; g++)
                acc[mi][ni][g] = 0.0f;

    for (int k0 = 0; k0 < Hh; k0 += BK) {
        // load h tile: 64 rows x 32 k  (512 float4, 4 per thread)
        #pragma unroll
        for (int it = 0; it < 4; it++) {
            int f  = tid + it * 128;
            int m  = f >> 3;
            int kk = f & 7;
            float4 v = *reinterpret_cast<const float4*>(
                &h_in[(size_t)(m0 + m) * Hh + k0 + kk * 4]);
            sh_h[kk * 4 + 0][m] = v.x;
            sh_h[kk * 4 + 1][m] = v.y;
            sh_h[kk * 4 + 2][m] = v.z;
            sh_h[kk * 4 + 3][m] = v.w;
        }
        // load W tile: 64 gate-rows x 32 k
        #pragma unroll
        for (int it = 0; it < 4; it++) {
            int f   = tid + it * 128;
            int row = f >> 3;            // g*16 + n
            int kk  = f & 7;
            int g   = row >> 4;
            int n   = row & 15;
            int j   = g * Hh + n0 + n;   // global gate row in WU_w
            float4 v = *reinterpret_cast<const float4*>(
                &WU_w[(size_t)j * KW + 4 + k0 + kk * 4]);
            int col = n * 4 + g;
            sh_w[kk * 4 + 0][col] = v.x;
            sh_w[kk * 4 + 1][col] = v.y;
            sh_w[kk * 4 + 2][col] = v.z;
            sh_w[kk * 4 + 3][col] = v.w;
        }
        __syncthreads();

        #pragma unroll
        for (int k = 0; k < BK; k++) {
            float4 hv  = *reinterpret_cast<const float4*>(&sh_h[k][ty * 4]);
            float4 wa  = *reinterpret_cast<const float4*>(&sh_w[k][tx * 8]);
            float4 wb4 = *reinterpret_cast<const float4*>(&sh_w[k][tx * 8 + 4]);
            float hm[4] = {hv.x, hv.y, hv.z, hv.w};
            float w0[4] = {wa.x, wa.y, wa.z, wa.w};
            float w1[4] = {wb4.x, wb4.y, wb4.z, wb4.w};
            #pragma unroll
            for (int mi = 0; mi < 4; mi++) {
                #pragma unroll
                for (int g = 0; g < 4; g++) {
                    acc[mi][0][g] = fmaf(hm[mi], w0[g], acc[mi][0][g]);
                    acc[mi][1][g] = fmaf(hm[mi], w1[g], acc[mi][1][g]);
                }
            }
        }
        __syncthreads();
    }

    // Epilogue: add x_prev/input columns + bias, apply LSTM pointwise.
    float xp0[4], xp1[4], in0v[4], in1v[4];
    #pragma unroll
    for (int mi = 0; mi < 4; mi++) {
        int b    = m0 + ty * 4 + mi;
        xp0[mi]  = g_x[b * 2 + 0];
        xp1[mi]  = g_x[b * 2 + 1];
        size_t ib = (size_t)b * Tt * INP + (size_t)t * INP;
        in0v[mi] = rnn_input[ib + 0];
        in1v[mi] = rnn_input[ib + 1];
    }

    #pragma unroll
    for (int ni = 0; ni < 2; ni++) {
        int n = n0 + tx * 2 + ni;
        float bias[4];
        float4 wx[4];
        #pragma unroll
        for (int g = 0; g < 4; g++) {
            int j   = g * Hh + n;
            bias[g] = WU_b[j];
            wx[g]   = *reinterpret_cast<const float4*>(&WU_w[(size_t)j * KW]);
        }
        #pragma unroll
        for (int mi = 0; mi < 4; mi++) {
            int b = m0 + ty * 4 + mi;
            float gate[4];
            #pragma unroll
            for (int g = 0; g < 4; g++) {
                gate[g] = acc[mi][ni][g] + bias[g]
                        + xp0[mi] * wx[g].x + xp1[mi] * wx[g].y
                        + in0v[mi] * wx[g].z + in1v[mi] * wx[g].w;
            }
            float ig = sigm(gate[0]);
            float fg = sigm(gate[1]);
            float gg = tanhf(gate[2]);
            float og = sigm(gate[3]);
            int idx  = b * Hh + n;
            float cn = fg * g_c[idx] + ig * gg;
            g_c[idx] = cn;
            float hn = og * tanhf(cn);
            h_out[idx] = hn;
            out[(size_t)b * Tt * Zz + (size_t)t * Zz + 2 + n] = hn;
        }
    }
}

// ---------------------------------------------------------------------------
// Kernel B: alpha/Wx projections (4 dots of length 1024 per batch row) +
// Van-der-Pol dynamics + x update + outputs/coefficients/mats writes.
// Grid: (B). Block: 128 threads.
// ---------------------------------------------------------------------------
__global__ __launch_bounds__(128) void alpha_x(
    const float* __restrict__ alpha_w, const float* __restrict__ alpha_b,
    const float* __restrict__ Wx_w,    const float* __restrict__ Wx_b,
    const float* __restrict__ rnn_input, const float* __restrict__ tau,
    float* __restrict__ out, int t)
{
    int b   = blockIdx.x;
    int tid = threadIdx.x;
    const float* __restrict__ h = g_h[(t & 1) ^ 1] + (size_t)b * Hh;

    float s0 = 0.f, s1 = 0.f, s2 = 0.f, s3 = 0.f;
    for (int k = tid; k < Hh; k += 128) {
        float hv = h[k];
        s0 = fmaf(hv, alpha_w[k],      s0);
        s1 = fmaf(hv, alpha_w[Hh + k], s1);
        s2 = fmaf(hv, Wx_w[k],         s2);
        s3 = fmaf(hv, Wx_w[Hh + k],    s3);
    }
    #pragma unroll
    for (int off = 16; off > 0; off >>= 1) {
        s0 += __shfl_down_sync(0xffffffffu, s0, off);
        s1 += __shfl_down_sync(0xffffffffu, s1, off);
        s2 += __shfl_down_sync(0xffffffffu, s2, off);
        s3 += __shfl_down_sync(0xffffffffu, s3, off);
    }
    __shared__ float red[4][4];
    if ((tid & 31) == 0) {
        int w = tid >> 5;
        red[w][0] = s0; red[w][1] = s1; red[w][2] = s2; red[w][3] = s3;
    }
    __syncthreads();
    if (tid == 0) {
        s0 = red[0][0] + red[1][0] + red[2][0] + red[3][0];
        s1 = red[0][1] + red[1][1] + red[2][1] + red[3][1];
        s2 = red[0][2] + red[1][2] + red[2][2] + red[3][2];
        s3 = red[0][3] + red[1][3] + red[2][3] + red[3][3];

        float x1 = g_x[b * 2 + 0];
        float x2 = g_x[b * 2 + 1];
        float u  = rnn_input[(size_t)b * Tt * INP + (size_t)t * INP];  // inp[:, :1]
        float ta = tau[(size_t)b * Tt + t];

        float a10 = -1.0f - 2.0f * x1 * x2;      // MHU = 1, DYN = 1
        float a11 = 1.0f - x1 * x1;
        float dx0 = x2;
        float dx1 = a10 * x1 + a11 * x2 + u;     // B_mat = [[0],[1]]
        float xm0 = x1 + ta * dx0;
        float xm1 = x2 + ta * dx1;

        float al0 = sigm(s0 + alpha_b[0]);
        float al1 = sigm(s1 + alpha_b[1]);
        float xn0 = (1.0f - al0) * xm0 + al0 * (s2 + Wx_b[0]);
        float xn1 = (1.0f - al1) * xm1 + al1 * (s3 + Wx_b[1]);

        g_x[b * 2 + 0] = xn0;
        g_x[b * 2 + 1] = xn1;

        size_t ob = (size_t)b * Tt * Zz + (size_t)t * Zz;
        out[ob + 0] = xn0;
        out[ob + 1] = xn1;
        size_t cb = COEF_OFF + (size_t)b * Tt * Ss + (size_t)t * Ss;
        out[cb + 0] = al0;
        out[cb + 1] = al1;
        if (b == 0) {
            size_t mb = MATS_OFF + (size_t)t * 4;
            out[mb + 0] = 0.0f;
            out[mb + 1] = 1.0f;
            out[mb + 2] = a10;
            out[mb + 3] = a11;
        }
    }
}

// ---------------------------------------------------------------------------
// finalize: zf = [x_final, h_final], czf = [c_z0[:, :2], c_final]
// ---------------------------------------------------------------------------
__global__ void finalize(const float* __restrict__ c_z0,
                         float* __restrict__ out) {
    int i = blockIdx.x * blockDim.x + threadIdx.x;
    if (i >= Bb * Zz) return;
    int b = i / Zz, z = i - b * Zz;
    float zv, cv;
    if (z < 2) {
        zv = g_x[b * 2 + z];
        cv = c_z0[(size_t)b * Zz + z];
    } else {
        // T=256 steps: step t writes g_h[(t+1)&1]; t=255 -> g_h[0]
        zv = g_h[0][(size_t)b * Hh + z - 2];
        cv = g_c[(size_t)b * Hh + z - 2];
    }
    out[ZF_OFF  + i] = zv;
    out[CZF_OFF + i] = cv;
}

// ---------------------------------------------------------------------------
extern "C" void kernel_launch(void* const* d_in, const int* in_sizes, int n_in,
                              void* d_out, int out_size) {
    const float* rnn_input = (const float*)d_in[0];
    const float* tau       = (const float*)d_in[1];
    const float* z0        = (const float*)d_in[2];
    const float* c_z0      = (const float*)d_in[3];
    const float* WU_w      = (const float*)d_in[4];
    const float* WU_b      = (const float*)d_in[5];
    const float* alpha_w   = (const float*)d_in[6];
    const float* alpha_b   = (const float*)d_in[7];
    const float* Wx_w      = (const float*)d_in[8];
    const float* Wx_b      = (const float*)d_in[9];
    float* out = (float*)d_out;

    init_state<<<(Bb * Hh + 255) / 256, 256>>>(z0, c_z0);

    dim3 gridA(Bb / BM, Hh / BHU);   // (4, 64)
    for (int t = 0; t < Tt; t++) {
        gates_lstm<<<gridA, 128>>>(WU_w, WU_b, rnn_input, out, t);
        alpha_x<<<Bb, 128>>>(alpha_w, alpha_b, Wx_w, Wx_b,
                             rnn_input, tau, out, t);
    }
    finalize<<<(Bb * Zz + 127) / 128, 128>>>(c_z0, out);
}